// round 16
// baseline (speedup 1.0000x reference)
#include <cuda_runtime.h>
#include <cuda_fp16.h>
#include <math.h>
#include <stdint.h>

// Problem constants
#define BATCH 4
#define NTOK 4096
#define DIM 1024
#define NHEAD 16
#define HD 64
#define MROWS (BATCH * NTOK)          // 16384
#define SCALE 0.125f                  // HD^-0.5
#define NCHUNK 4

// ---------------------------------------------------------------------------
// Scratch buffers
// ---------------------------------------------------------------------------
__device__ __half g_x_h [MROWS * DIM];
__device__ __half g_hq_h[MROWS * DIM];
__device__ __half g_hk_h[MROWS * DIM];
__device__ __half g_y_h [MROWS * DIM];
__device__ __half g_q [MROWS * DIM];
__device__ __half g_k [MROWS * DIM];
__device__ __half g_v [MROWS * DIM];
__device__ __half g_g [MROWS * DIM];
__device__ __half g_A_h[BATCH * NHEAD * HD * HD];
__device__ float g_z [BATCH * NHEAD * HD];
__device__ float g_Ap[NCHUNK * BATCH * NHEAD * HD * HD];
__device__ __half g_w_h [7 * DIM * DIM];   // q1|q2|k1|k2|v|g|p

// ---------------------------------------------------------------------------
// PTX helpers
// ---------------------------------------------------------------------------
__device__ __forceinline__ uint32_t smem_u32(const void* p) {
    uint32_t a;
    asm("{ .reg .u64 t; cvta.to.shared.u64 t, %1; cvt.u32.u64 %0, t; }" : "=r"(a) : "l"(p));
    return a;
}
#define SWZ(o) ((o) ^ (((o) >> 3) & 0x70))

__device__ __forceinline__ void cp16(uint32_t saddr, const void* g) {
    asm volatile("cp.async.cg.shared.global [%0], [%1], 16;" :: "r"(saddr), "l"(g));
}
#define CP_COMMIT() asm volatile("cp.async.commit_group;" ::: "memory")
#define CP_WAIT(N)  asm volatile("cp.async.wait_group %0;" :: "n"(N) : "memory")

#define LDSM4(r, a) \
    asm volatile("ldmatrix.sync.aligned.m8n8.x4.shared.b16 {%0,%1,%2,%3}, [%4];" \
        : "=r"((r)[0]), "=r"((r)[1]), "=r"((r)[2]), "=r"((r)[3]) : "r"(a))

#define LDSM4T(r, a) \
    asm volatile("ldmatrix.sync.aligned.m8n8.x4.trans.shared.b16 {%0,%1,%2,%3}, [%4];" \
        : "=r"((r)[0]), "=r"((r)[1]), "=r"((r)[2]), "=r"((r)[3]) : "r"(a))

#define MMA16816F(c, a, b) \
    asm volatile("mma.sync.aligned.m16n8k16.row.col.f32.f16.f16.f32 " \
        "{%0,%1,%2,%3}, {%4,%5,%6,%7}, {%8,%9}, {%0,%1,%2,%3};" \
        : "+f"((c)[0]), "+f"((c)[1]), "+f"((c)[2]), "+f"((c)[3]) \
        : "r"((a)[0]), "r"((a)[1]), "r"((a)[2]), "r"((a)[3]), \
          "r"((b)[0]), "r"((b)[1]))

// ---------------------------------------------------------------------------
// Activations
// ---------------------------------------------------------------------------
__device__ __forceinline__ float gelu_f(float x) {
    return 0.5f * x * (1.0f + erff(x * 0.70710678118654752440f));
}
__device__ __forceinline__ float softplus_f(float x) {
    return fmaxf(x, 0.0f) + log1pf(__expf(-fabsf(x)));
}
__device__ __forceinline__ uint32_t pack2h(float a, float b) {
    __half2 h = __halves2half2(__float2half_rn(a), __float2half_rn(b));
    return *(uint32_t*)&h;
}

// ---------------------------------------------------------------------------
// fp32 -> fp16 convert
// ---------------------------------------------------------------------------
__global__ __launch_bounds__(256)
void conv_f2h_w(const float4* __restrict__ src, uint4* __restrict__ dst, int n8)
{
    const int stride = gridDim.x * blockDim.x;
    for (int i = blockIdx.x * blockDim.x + threadIdx.x; i < n8; i += stride) {
        float4 a = src[2 * i];
        float4 b = src[2 * i + 1];
        uint4 d;
        d.x = pack2h(a.x, a.y);
        d.y = pack2h(a.z, a.w);
        d.z = pack2h(b.x, b.y);
        d.w = pack2h(b.z, b.w);
        dst[i] = d;
    }
}

// ---------------------------------------------------------------------------
// HMMA fp16 GEMM v2: CTA tile 128x256, BK=64, 3-stage cp.async,
// 8 warps (2m x 4n), warp tile 64x64 (4 m-frag x 8 n-frag). 1 CTA/SM.
// ---------------------------------------------------------------------------
#define A_TILE_B 16384                  // 128 x 64 fp16
#define B_TILE_B 32768                  // 256 x 64 fp16
#define STAGE_B (A_TILE_B + B_TILE_B)   // 49152
#define NSTAGE 3
#define GSMEM_TOTAL (NSTAGE * STAGE_B)  // 147456

__global__ __launch_bounds__(256, 1)
void gemm_mma(const __half* __restrict__ A, const __half* __restrict__ Wh,
              const float* __restrict__ bias, int act, int outmode,
              float* __restrict__ Cf, __half* __restrict__ Ch)
{
    extern __shared__ char smem[];
    const uint32_t sb = smem_u32(smem);
    const int t    = threadIdx.x;
    const int lane = t & 31;
    const int w    = t >> 5;
    const int wm   = w >> 2;          // 2 m-warps
    const int wn   = w & 3;           // 4 n-warps
    const int m0   = blockIdx.y * 128;
    const int n0   = blockIdx.x * 256;

    const int lu   = t & 7;           // 16B unit within row
    const int lr   = t >> 3;          // 0..31

    auto issue = [&](int stage, int kc) {
        const uint32_t sA = sb + stage * STAGE_B;
        const uint32_t sB = sA + A_TILE_B;
        const int kbase = kc * 64 + lu * 8;
#pragma unroll
        for (int i = 0; i < 4; i++) {   // A: 128 rows
            const int row = lr + i * 32;
            cp16(sA + SWZ((uint32_t)(row * 128 + lu * 16)),
                 A + (size_t)(m0 + row) * DIM + kbase);
        }
#pragma unroll
        for (int i = 0; i < 8; i++) {   // B: 256 rows
            const int row = lr + i * 32;
            cp16(sB + SWZ((uint32_t)(row * 128 + lu * 16)),
                 Wh + (size_t)(n0 + row) * DIM + kbase);
        }
        CP_COMMIT();
    };

    issue(0, 0);
    issue(1, 1);

    float acc[4][8][4];
#pragma unroll
    for (int im = 0; im < 4; im++)
#pragma unroll
        for (int in = 0; in < 8; in++)
#pragma unroll
            for (int j = 0; j < 4; j++) acc[im][in][j] = 0.0f;

    const int g  = lane >> 3;
    const int rr = lane & 7;

    for (int kc = 0; kc < 16; kc++) {
        if (kc == 15) { CP_WAIT(0); } else { CP_WAIT(1); }
        __syncthreads();
        if (kc + 2 < 16) issue((kc + 2) % NSTAGE, kc + 2);

        const uint32_t sA = sb + (kc % NSTAGE) * STAGE_B;
        const uint32_t sB = sA + A_TILE_B;
#pragma unroll
        for (int kk = 0; kk < 4; kk++) {
            const int ku = kk * 2 + (g >> 1);
            uint32_t ah[4][4];
#pragma unroll
            for (int im = 0; im < 4; im++) {
                const int row = wm * 64 + im * 16 + (g & 1) * 8 + rr;
                LDSM4(ah[im], sA + SWZ((uint32_t)(row * 128 + ku * 16)));
            }
            uint32_t bh[8][2];
#pragma unroll
            for (int in2 = 0; in2 < 4; in2++) {
                const int row = wn * 64 + in2 * 16 + (g & 1) * 8 + rr;
                uint32_t qh[4];
                LDSM4(qh, sB + SWZ((uint32_t)(row * 128 + ku * 16)));
                bh[2 * in2][0] = qh[0]; bh[2 * in2][1] = qh[2];
                bh[2 * in2 + 1][0] = qh[1]; bh[2 * in2 + 1][1] = qh[3];
            }
#pragma unroll
            for (int im = 0; im < 4; im++)
#pragma unroll
                for (int in = 0; in < 8; in++)
                    MMA16816F(acc[im][in], ah[im], bh[in]);
        }
    }

    // ------ epilogue ------
    const int r0 = lane >> 2;
    const int c0 = (lane & 3) * 2;
#pragma unroll
    for (int im = 0; im < 4; im++) {
#pragma unroll
        for (int in = 0; in < 8; in++) {
            const int ncol = n0 + wn * 64 + in * 8 + c0;
            const float b0 = __ldg(&bias[ncol]);
            const float b1 = __ldg(&bias[ncol + 1]);
#pragma unroll
            for (int half = 0; half < 2; half++) {
                const int mrow = m0 + wm * 64 + im * 16 + r0 + half * 8;
                float v0 = acc[im][in][half * 2]     + b0;
                float v1 = acc[im][in][half * 2 + 1] + b1;
                if (act == 1)      { v0 = gelu_f(v0);     v1 = gelu_f(v1); }
                else if (act == 2) { v0 = softplus_f(v0); v1 = softplus_f(v1); }
                if (outmode == 0) {
                    *(float2*)(Cf + (size_t)mrow * DIM + ncol) = make_float2(v0, v1);
                } else {
                    *(__half2*)(Ch + (size_t)mrow * DIM + ncol) =
                        __halves2half2(__float2half_rn(v0), __float2half_rn(v1));
                }
            }
        }
    }
}

// ---------------------------------------------------------------------------
// Tensor-core attention pass 1 (unchanged from R15)
// ---------------------------------------------------------------------------
#define P1_STAGE 16384
#define P1_SMEM (2 * P1_STAGE)

__global__ __launch_bounds__(128)
void attn_pass1t(const __half* __restrict__ q, const __half* __restrict__ k,
                 float* __restrict__ Ap)
{
    extern __shared__ char smem[];
    const uint32_t sb = smem_u32(smem);
    const int bh = blockIdx.x, ch = blockIdx.y;
    const int b = bh >> 4, h = bh & 15;
    const __half* qb = q + (size_t)b * NTOK * DIM + h * HD;
    const __half* kb = k + (size_t)b * NTOK * DIM + h * HD;
    const int t = threadIdx.x, lane = t & 31, w = t >> 5;
    const int lu = t & 7, lr0 = t >> 3;
    const int cbase = ch * (NTOK / NCHUNK);

    auto issue = [&](int stage, int it) {
        const uint32_t sbq = sb + stage * P1_STAGE;
        const uint32_t sbk = sbq + 8192;
        const int c0 = cbase + it * 64;
#pragma unroll
        for (int i = 0; i < 4; i++) {
            const int row = lr0 + i * 16;
            const uint32_t so = SWZ((uint32_t)(row * 128 + lu * 16));
            cp16(sbq + so, qb + (size_t)(c0 + row) * DIM + lu * 8);
            cp16(sbk + so, kb + (size_t)(c0 + row) * DIM + lu * 8);
        }
        CP_COMMIT();
    };

    issue(0, 0);
    issue(1, 1);

    float acc[8][4];
#pragma unroll
    for (int in = 0; in < 8; in++)
#pragma unroll
        for (int j = 0; j < 4; j++) acc[in][j] = 0.0f;

    const int g  = lane >> 3, rr = lane & 7;
    const int toksel = ((g >> 1) << 3) + rr;
    const int dimsel = (g & 1) << 3;

    for (int it = 0; it < 16; it++) {
        if (it == 15) { CP_WAIT(0); } else { CP_WAIT(1); }
        __syncthreads();
        const uint32_t stq = sb + (it & 1) * P1_STAGE;
        const uint32_t stk = stq + 8192;
#pragma unroll
        for (int ks = 0; ks < 4; ks++) {
            const int tok = ks * 16 + toksel;
            uint32_t ah[4];
            LDSM4T(ah, stq + SWZ((uint32_t)(tok * 128 + (w * 16 + dimsel) * 2)));
            uint32_t bh2[8][2];
#pragma unroll
            for (int jb = 0; jb < 4; jb++) {
                uint32_t qh[4];
                LDSM4T(qh, stk + SWZ((uint32_t)(tok * 128 + (jb * 16 + dimsel) * 2)));
                bh2[2 * jb][0] = qh[0]; bh2[2 * jb][1] = qh[2];
                bh2[2 * jb + 1][0] = qh[1]; bh2[2 * jb + 1][1] = qh[3];
            }
#pragma unroll
            for (int in = 0; in < 8; in++)
                MMA16816F(acc[in], ah, bh2[in]);
        }
        if (it + 2 < 16) { __syncthreads(); issue(it & 1, it + 2); }
    }

    const int r0 = lane >> 2, cp = (lane & 3) * 2;
    float* Abh = Ap + ((size_t)ch * 64 + bh) * (HD * HD);
#pragma unroll
    for (int in = 0; in < 8; in++) {
        const int m = in * 8 + cp;
#pragma unroll
        for (int half = 0; half < 2; half++) {
            const int n = w * 16 + r0 + half * 8;
            *(float2*)(Abh + n * 64 + m) =
                make_float2(acc[in][half * 2], acc[in][half * 2 + 1]);
        }
    }
}

// ---------------------------------------------------------------------------
// Reduce partials -> A fp16 + z
// ---------------------------------------------------------------------------
__global__ __launch_bounds__(256)
void attn_reduce(const float* __restrict__ Ap, __half* __restrict__ Ah,
                 float* __restrict__ gZ)
{
    const int bh = blockIdx.x, t = threadIdx.x;
    const int row = t >> 2, qp = t & 3;
    float s[16];
#pragma unroll
    for (int j = 0; j < 16; j++) s[j] = 0.0f;
    for (int c = 0; c < NCHUNK; c++) {
        const float* p = Ap + ((size_t)c * 64 + bh) * (HD * HD) + row * 64 + qp * 16;
#pragma unroll
        for (int j = 0; j < 16; j += 4) {
            float4 v4 = *(const float4*)(p + j);
            s[j] += v4.x; s[j + 1] += v4.y; s[j + 2] += v4.z; s[j + 3] += v4.w;
        }
    }
    alignas(16) __half hv[16];
    float rp = 0.0f;
#pragma unroll
    for (int j = 0; j < 16; j++) { rp += s[j]; hv[j] = __float2half_rn(s[j]); }
    uint4* dst = (uint4*)(Ah + (size_t)bh * (HD * HD) + row * 64 + qp * 16);
    dst[0] = ((uint4*)hv)[0];
    dst[1] = ((uint4*)hv)[1];
    rp += __shfl_xor_sync(0xffffffffu, rp, 1);
    rp += __shfl_xor_sync(0xffffffffu, rp, 2);
    if (qp == 0)
        gZ[bh * HD + row] = 1.0f / (SCALE * rp + (float)DIM);
}

// ---------------------------------------------------------------------------
// Tensor-core attention pass 2 (unchanged from R15)
// ---------------------------------------------------------------------------
__global__ __launch_bounds__(128)
void attn_pass2t(const __half* __restrict__ v, const __half* __restrict__ gg,
                 const __half* __restrict__ Ah, const float* __restrict__ gZ,
                 __half* __restrict__ Yh)
{
    __shared__ __align__(16) char As_s[8192];
    __shared__ __align__(16) char vs_s[8192];
    __shared__ float zs[64];
    const int bh = blockIdx.x, b = bh >> 4, h = bh & 15;
    const int c0 = blockIdx.y * 64;
    const int t = threadIdx.x, lane = t & 31, w = t >> 5;
    const uint32_t sA = smem_u32(As_s), sV = smem_u32(vs_s);

    {
        const uint4* Ag = (const uint4*)(Ah + (size_t)bh * (HD * HD));
        const __half* vb = v + (size_t)(b * NTOK + c0) * DIM + h * HD;
        for (int i = t; i < 512; i += 128) {
            const int row = i >> 3, un = i & 7;
            const uint32_t so = SWZ((uint32_t)(row * 128 + un * 16));
            *(uint4*)(As_s + so) = Ag[i];
            *(uint4*)(vs_s + so) = *(const uint4*)(vb + (size_t)row * DIM + un * 8);
        }
        if (t < 64) zs[t] = gZ[bh * HD + t];
    }
    __syncthreads();

    float acc[8][4];
#pragma unroll
    for (int in = 0; in < 8; in++)
#pragma unroll
        for (int j = 0; j < 4; j++) acc[in][j] = 0.0f;

    const int g = lane >> 3, rr = lane & 7;
#pragma unroll
    for (int ks = 0; ks < 4; ks++) {
        const int ku = ks * 2 + (g >> 1);
        uint32_t ah[4];
        {
            const int row = w * 16 + ((g & 1) << 3) + rr;
            LDSM4(ah, sV + SWZ((uint32_t)(row * 128 + ku * 16)));
        }
        uint32_t bh2[8][2];
#pragma unroll
        for (int jb = 0; jb < 4; jb++) {
            const int row = jb * 16 + ((g & 1) << 3) + rr;
            uint32_t qh[4];
            LDSM4(qh, sA + SWZ((uint32_t)(row * 128 + ku * 16)));
            bh2[2 * jb][0] = qh[0]; bh2[2 * jb][1] = qh[2];
            bh2[2 * jb + 1][0] = qh[1]; bh2[2 * jb + 1][1] = qh[3];
        }
#pragma unroll
        for (int in = 0; in < 8; in++)
            MMA16816F(acc[in], ah, bh2[in]);
    }

    const int r0 = lane >> 2, cp = (lane & 3) * 2;
#pragma unroll
    for (int in = 0; in < 8; in++) {
        const int n = in * 8 + cp;
#pragma unroll
        for (int half = 0; half < 2; half++) {
            const int dl = w * 16 + r0 + half * 8;
            const int tok = c0 + dl;
            __half2 vv = *(__half2*)(vs_s + SWZ((uint32_t)(dl * 128 + n * 2)));
            float2 vf = __half22float2(vv);
            __half2 gv = *(const __half2*)(gg + (size_t)(b * NTOK + tok) * DIM + h * HD + n);
            float2 gf = __half22float2(gv);
            float o0 = (SCALE * acc[in][half * 2]     + vf.x) * zs[n]     * gf.x;
            float o1 = (SCALE * acc[in][half * 2 + 1] + vf.y) * zs[n + 1] * gf.y;
            const int row = b * NTOK + h * 256 + (tok >> 4);
            const int col = ((tok & 15) << 6) + n;
            *(__half2*)(Yh + (size_t)row * DIM + col) =
                __halves2half2(__float2half_rn(o0), __float2half_rn(o1));
        }
    }
}

// ---------------------------------------------------------------------------
// Launch — gemm at enqueue position 6 (for ncu -s 5 -c 1)
// ---------------------------------------------------------------------------
extern "C" void kernel_launch(void* const* d_in, const int* in_sizes, int n_in,
                              void* d_out, int out_size)
{
    const float* x    = (const float*)d_in[0];
    const float* q_w1 = (const float*)d_in[1];
    const float* q_b1 = (const float*)d_in[2];
    const float* q_w2 = (const float*)d_in[3];
    const float* q_b2 = (const float*)d_in[4];
    const float* k_w1 = (const float*)d_in[5];
    const float* k_b1 = (const float*)d_in[6];
    const float* k_w2 = (const float*)d_in[7];
    const float* k_b2 = (const float*)d_in[8];
    const float* v_w  = (const float*)d_in[9];
    const float* v_b  = (const float*)d_in[10];
    const float* g_w  = (const float*)d_in[11];
    const float* g_b  = (const float*)d_in[12];
    const float* p_w  = (const float*)d_in[13];
    const float* p_b  = (const float*)d_in[14];
    float* out = (float*)d_out;

    __half *xh, *hqh, *hkh, *yh, *wh, *qb, *kb, *vb, *gb, *Ahp;
    float *zb, *Apb;
    cudaGetSymbolAddress((void**)&xh,  g_x_h);
    cudaGetSymbolAddress((void**)&hqh, g_hq_h);
    cudaGetSymbolAddress((void**)&hkh, g_hk_h);
    cudaGetSymbolAddress((void**)&yh,  g_y_h);
    cudaGetSymbolAddress((void**)&wh,  g_w_h);
    cudaGetSymbolAddress((void**)&qb,  g_q);
    cudaGetSymbolAddress((void**)&kb,  g_k);
    cudaGetSymbolAddress((void**)&vb,  g_v);
    cudaGetSymbolAddress((void**)&gb,  g_g);
    cudaGetSymbolAddress((void**)&Ahp, g_A_h);
    cudaGetSymbolAddress((void**)&zb,  g_z);
    cudaGetSymbolAddress((void**)&Apb, g_Ap);

    static bool init_done = false;
    static cudaStream_t s1, s2, s3;
    static cudaEvent_t ev_fork, ev_x, ev_qw1, ev_qw2, ev_kw1, ev_kw2,
                       ev_vw, ev_gw, ev_pw, ev_k2, ev_v, ev_g;
    if (!init_done) {
        cudaFuncSetAttribute(gemm_mma, cudaFuncAttributeMaxDynamicSharedMemorySize, GSMEM_TOTAL);
        cudaStreamCreateWithFlags(&s1, cudaStreamNonBlocking);
        cudaStreamCreateWithFlags(&s2, cudaStreamNonBlocking);
        cudaStreamCreateWithFlags(&s3, cudaStreamNonBlocking);
        cudaEventCreateWithFlags(&ev_fork, cudaEventDisableTiming);
        cudaEventCreateWithFlags(&ev_x,    cudaEventDisableTiming);
        cudaEventCreateWithFlags(&ev_qw1,  cudaEventDisableTiming);
        cudaEventCreateWithFlags(&ev_qw2,  cudaEventDisableTiming);
        cudaEventCreateWithFlags(&ev_kw1,  cudaEventDisableTiming);
        cudaEventCreateWithFlags(&ev_kw2,  cudaEventDisableTiming);
        cudaEventCreateWithFlags(&ev_vw,   cudaEventDisableTiming);
        cudaEventCreateWithFlags(&ev_gw,   cudaEventDisableTiming);
        cudaEventCreateWithFlags(&ev_pw,   cudaEventDisableTiming);
        cudaEventCreateWithFlags(&ev_k2,   cudaEventDisableTiming);
        cudaEventCreateWithFlags(&ev_v,    cudaEventDisableTiming);
        cudaEventCreateWithFlags(&ev_g,    cudaEventDisableTiming);
        init_done = true;
    }

    const int WSZ = DIM * DIM;
    const int W8  = WSZ / 8;
#define WH(i) (wh + (size_t)(i) * WSZ)

    dim3 ggrid(DIM / 256, MROWS / 128);   // (4, 128) = 512 CTAs

    // === fork ===
    cudaEventRecord(ev_fork, 0);
    cudaStreamWaitEvent(s1, ev_fork, 0);
    cudaStreamWaitEvent(s2, ev_fork, 0);
    cudaStreamWaitEvent(s3, ev_fork, 0);

    // #1: x convert (s0, critical head)
    conv_f2h_w<<<2048, 256>>>((const float4*)x, (uint4*)xh, MROWS * DIM / 8);
    cudaEventRecord(ev_x, 0);

    // #2-#5: q/k weight converts
    conv_f2h_w<<<592, 256, 0, s1>>>((const float4*)q_w1, (uint4*)WH(0), W8);
    cudaEventRecord(ev_qw1, s1);
    conv_f2h_w<<<592, 256, 0, s1>>>((const float4*)q_w2, (uint4*)WH(1), W8);
    cudaEventRecord(ev_qw2, s1);
    conv_f2h_w<<<592, 256, 0, s2>>>((const float4*)k_w1, (uint4*)WH(2), W8);
    cudaEventRecord(ev_kw1, s2);
    conv_f2h_w<<<592, 256, 0, s2>>>((const float4*)k_w2, (uint4*)WH(3), W8);
    cudaEventRecord(ev_kw2, s2);

    // #6: FIRST GEMM (q1) — the launch ncu profiles
    cudaStreamWaitEvent(0, ev_qw1, 0);
    gemm_mma<<<ggrid, 256, GSMEM_TOTAL>>>(xh, WH(0), q_b1, 1, 1, nullptr, hqh);

    // remaining converts
    conv_f2h_w<<<592, 256, 0, s2>>>((const float4*)v_w, (uint4*)WH(4), W8);
    cudaEventRecord(ev_vw, s2);
    conv_f2h_w<<<592, 256, 0, s3>>>((const float4*)g_w, (uint4*)WH(5), W8);
    cudaEventRecord(ev_gw, s3);
    conv_f2h_w<<<592, 256, 0, s3>>>((const float4*)p_w, (uint4*)WH(6), W8);
    cudaEventRecord(ev_pw, s3);

    // k chain on s1
    cudaStreamWaitEvent(s1, ev_x, 0);
    cudaStreamWaitEvent(s1, ev_kw1, 0);
    gemm_mma<<<ggrid, 256, GSMEM_TOTAL, s1>>>(xh, WH(2), k_b1, 1, 1, nullptr, hkh);
    // q2 on s0
    cudaStreamWaitEvent(0, ev_qw2, 0);
    gemm_mma<<<ggrid, 256, GSMEM_TOTAL>>>(hqh, WH(1), q_b2, 2, 1, nullptr, qb);
    // k2 on s1
    cudaStreamWaitEvent(s1, ev_kw2, 0);
    gemm_mma<<<ggrid, 256, GSMEM_TOTAL, s1>>>(hkh, WH(3), k_b2, 2, 1, nullptr, kb);
    cudaEventRecord(ev_k2, s1);

    // v, g GEMMs trail (overlap with attention pass 1)
    cudaStreamWaitEvent(s2, ev_x, 0);
    gemm_mma<<<ggrid, 256, GSMEM_TOTAL, s2>>>(xh, WH(4), v_b, 1, 1, nullptr, vb);
    cudaEventRecord(ev_v, s2);
    cudaStreamWaitEvent(s3, ev_x, 0);
    gemm_mma<<<ggrid, 256, GSMEM_TOTAL, s3>>>(xh, WH(5), g_b, 1, 1, nullptr, gb);
    cudaEventRecord(ev_g, s3);

    // attention (tensor-core)
    cudaStreamWaitEvent(0, ev_k2, 0);
    attn_pass1t<<<dim3(BATCH * NHEAD, NCHUNK), 128, P1_SMEM>>>(qb, kb, Apb);
    attn_reduce<<<BATCH * NHEAD, 256>>>(Apb, Ahp, zb);

    cudaStreamWaitEvent(0, ev_v, 0);
    cudaStreamWaitEvent(0, ev_g, 0);
    attn_pass2t<<<dim3(BATCH * NHEAD, NTOK / 64), 128>>>(vb, gb, Ahp, zb, yh);

    // final projection
    cudaStreamWaitEvent(0, ev_pw, 0);
    gemm_mma<<<ggrid, 256, GSMEM_TOTAL>>>(yh, WH(6), p_b, 0, 0, out, nullptr);
}

// round 17
// speedup vs baseline: 1.2657x; 1.2657x over previous
#include <cuda_runtime.h>
#include <cuda_fp16.h>
#include <math.h>
#include <stdint.h>

// Problem constants
#define BATCH 4
#define NTOK 4096
#define DIM 1024
#define NHEAD 16
#define HD 64
#define MROWS (BATCH * NTOK)          // 16384
#define SCALE 0.125f                  // HD^-0.5
#define NCHUNK 4

// ---------------------------------------------------------------------------
// Scratch buffers
// ---------------------------------------------------------------------------
__device__ __half g_x_h [MROWS * DIM];
__device__ __half g_hq_h[MROWS * DIM];
__device__ __half g_hk_h[MROWS * DIM];
__device__ __half g_y_h [MROWS * DIM];
__device__ __half g_q [MROWS * DIM];
__device__ __half g_k [MROWS * DIM];
__device__ __half g_v [MROWS * DIM];
__device__ __half g_g [MROWS * DIM];
__device__ __half g_A_h[BATCH * NHEAD * HD * HD];
__device__ float g_z [BATCH * NHEAD * HD];
__device__ float g_Ap[NCHUNK * BATCH * NHEAD * HD * HD];
__device__ __half g_w_h [7 * DIM * DIM];   // q1|q2|k1|k2|v|g|p

// ---------------------------------------------------------------------------
// PTX helpers
// ---------------------------------------------------------------------------
__device__ __forceinline__ uint32_t smem_u32(const void* p) {
    uint32_t a;
    asm("{ .reg .u64 t; cvta.to.shared.u64 t, %1; cvt.u32.u64 %0, t; }" : "=r"(a) : "l"(p));
    return a;
}
#define SWZ(o) ((o) ^ (((o) >> 3) & 0x70))

__device__ __forceinline__ void cp16(uint32_t saddr, const void* g) {
    asm volatile("cp.async.cg.shared.global [%0], [%1], 16;" :: "r"(saddr), "l"(g));
}
#define CP_COMMIT() asm volatile("cp.async.commit_group;" ::: "memory")
#define CP_WAIT(N)  asm volatile("cp.async.wait_group %0;" :: "n"(N) : "memory")

#define LDSM4(r, a) \
    asm volatile("ldmatrix.sync.aligned.m8n8.x4.shared.b16 {%0,%1,%2,%3}, [%4];" \
        : "=r"((r)[0]), "=r"((r)[1]), "=r"((r)[2]), "=r"((r)[3]) : "r"(a))

#define LDSM4T(r, a) \
    asm volatile("ldmatrix.sync.aligned.m8n8.x4.trans.shared.b16 {%0,%1,%2,%3}, [%4];" \
        : "=r"((r)[0]), "=r"((r)[1]), "=r"((r)[2]), "=r"((r)[3]) : "r"(a))

#define MMA16816F(c, a, b) \
    asm volatile("mma.sync.aligned.m16n8k16.row.col.f32.f16.f16.f32 " \
        "{%0,%1,%2,%3}, {%4,%5,%6,%7}, {%8,%9}, {%0,%1,%2,%3};" \
        : "+f"((c)[0]), "+f"((c)[1]), "+f"((c)[2]), "+f"((c)[3]) \
        : "r"((a)[0]), "r"((a)[1]), "r"((a)[2]), "r"((a)[3]), \
          "r"((b)[0]), "r"((b)[1]))

// ---------------------------------------------------------------------------
// Activations
// ---------------------------------------------------------------------------
__device__ __forceinline__ float gelu_f(float x) {
    return 0.5f * x * (1.0f + erff(x * 0.70710678118654752440f));
}
__device__ __forceinline__ float softplus_f(float x) {
    return fmaxf(x, 0.0f) + log1pf(__expf(-fabsf(x)));
}
__device__ __forceinline__ uint32_t pack2h(float a, float b) {
    __half2 h = __halves2half2(__float2half_rn(a), __float2half_rn(b));
    return *(uint32_t*)&h;
}

// ---------------------------------------------------------------------------
// fp32 -> fp16 convert
// ---------------------------------------------------------------------------
__global__ __launch_bounds__(256)
void conv_f2h_w(const float4* __restrict__ src, uint4* __restrict__ dst, int n8)
{
    const int stride = gridDim.x * blockDim.x;
    for (int i = blockIdx.x * blockDim.x + threadIdx.x; i < n8; i += stride) {
        float4 a = src[2 * i];
        float4 b = src[2 * i + 1];
        uint4 d;
        d.x = pack2h(a.x, a.y);
        d.y = pack2h(a.z, a.w);
        d.z = pack2h(b.x, b.y);
        d.w = pack2h(b.z, b.w);
        dst[i] = d;
    }
}

// ---------------------------------------------------------------------------
// HMMA fp16 GEMM (R15 champion core: 128x128, 8 warps 4m x 2n, 3-stage,
// 2 CTAs/SM)
// ---------------------------------------------------------------------------
#define TILE_B 16384
#define STAGE_B (2 * TILE_B)
#define NSTAGE 3
#define GSMEM_TOTAL (NSTAGE * STAGE_B)  // 98304

__global__ __launch_bounds__(256, 2)
void gemm_mma(const __half* __restrict__ A, const __half* __restrict__ Wh,
              const float* __restrict__ bias, int act, int outmode,
              float* __restrict__ Cf, __half* __restrict__ Ch)
{
    extern __shared__ char smem[];
    const uint32_t sb = smem_u32(smem);
    const int t    = threadIdx.x;
    const int lane = t & 31;
    const int w    = t >> 5;
    const int wm   = w & 3;
    const int wn   = w >> 2;
    const int m0   = blockIdx.y * 128;
    const int n0   = blockIdx.x * 128;

    const int lrow = t >> 3;
    const int lu   = t & 7;

    auto issue = [&](int stage, int kc) {
        const uint32_t sbase = sb + stage * STAGE_B;
        const int kbase = kc * 64 + lu * 8;
#pragma unroll
        for (int i = 0; i < 4; i++) {
            const int row = lrow + i * 32;
            const uint32_t soff = SWZ((uint32_t)(row * 128 + lu * 16));
            cp16(sbase + soff,          A  + (size_t)(m0 + row) * DIM + kbase);
            cp16(sbase + TILE_B + soff, Wh + (size_t)(n0 + row) * DIM + kbase);
        }
        CP_COMMIT();
    };

    issue(0, 0);
    issue(1, 1);

    float acc[2][8][4];
#pragma unroll
    for (int im = 0; im < 2; im++)
#pragma unroll
        for (int in = 0; in < 8; in++)
#pragma unroll
            for (int j = 0; j < 4; j++) acc[im][in][j] = 0.0f;

    const int g  = lane >> 3;
    const int rr = lane & 7;

    for (int kc = 0; kc < 16; kc++) {
        if (kc == 15) { CP_WAIT(0); } else { CP_WAIT(1); }
        __syncthreads();
        if (kc + 2 < 16) issue((kc + 2) % NSTAGE, kc + 2);

        const uint32_t st = sb + (kc % NSTAGE) * STAGE_B;
#pragma unroll
        for (int kk = 0; kk < 4; kk++) {
            const int ku = kk * 2 + (g >> 1);
            uint32_t ah[2][4];
#pragma unroll
            for (int im = 0; im < 2; im++) {
                const int row = wm * 32 + im * 16 + (g & 1) * 8 + rr;
                const uint32_t off = SWZ((uint32_t)(row * 128 + ku * 16));
                LDSM4(ah[im], st + off);
            }
            uint32_t bh[8][2];
#pragma unroll
            for (int in2 = 0; in2 < 4; in2++) {
                const int row = wn * 64 + in2 * 16 + (g & 1) * 8 + rr;
                const uint32_t off = SWZ((uint32_t)(row * 128 + ku * 16));
                uint32_t qh[4];
                LDSM4(qh, st + TILE_B + off);
                bh[2 * in2][0] = qh[0]; bh[2 * in2][1] = qh[2];
                bh[2 * in2 + 1][0] = qh[1]; bh[2 * in2 + 1][1] = qh[3];
            }
#pragma unroll
            for (int im = 0; im < 2; im++)
#pragma unroll
                for (int in = 0; in < 8; in++)
                    MMA16816F(acc[im][in], ah[im], bh[in]);
        }
    }

    const int r0 = lane >> 2;
    const int c0 = (lane & 3) * 2;
#pragma unroll
    for (int im = 0; im < 2; im++) {
#pragma unroll
        for (int in = 0; in < 8; in++) {
            const int ncol = n0 + wn * 64 + in * 8 + c0;
            const float b0 = __ldg(&bias[ncol]);
            const float b1 = __ldg(&bias[ncol + 1]);
#pragma unroll
            for (int half = 0; half < 2; half++) {
                const int mrow = m0 + wm * 32 + im * 16 + r0 + half * 8;
                float v0 = acc[im][in][half * 2]     + b0;
                float v1 = acc[im][in][half * 2 + 1] + b1;
                if (act == 1)      { v0 = gelu_f(v0);     v1 = gelu_f(v1); }
                else if (act == 2) { v0 = softplus_f(v0); v1 = softplus_f(v1); }
                if (outmode == 0) {
                    *(float2*)(Cf + (size_t)mrow * DIM + ncol) = make_float2(v0, v1);
                } else {
                    *(__half2*)(Ch + (size_t)mrow * DIM + ncol) =
                        __halves2half2(__float2half_rn(v0), __float2half_rn(v1));
                }
            }
        }
    }
}

// ---------------------------------------------------------------------------
// Tensor-core attention pass 1 (R15)
// ---------------------------------------------------------------------------
#define P1_STAGE 16384
#define P1_SMEM (2 * P1_STAGE)

__global__ __launch_bounds__(128)
void attn_pass1t(const __half* __restrict__ q, const __half* __restrict__ k,
                 float* __restrict__ Ap)
{
    extern __shared__ char smem[];
    const uint32_t sb = smem_u32(smem);
    const int bh = blockIdx.x, ch = blockIdx.y;
    const int b = bh >> 4, h = bh & 15;
    const __half* qb = q + (size_t)b * NTOK * DIM + h * HD;
    const __half* kb = k + (size_t)b * NTOK * DIM + h * HD;
    const int t = threadIdx.x, lane = t & 31, w = t >> 5;
    const int lu = t & 7, lr0 = t >> 3;
    const int cbase = ch * (NTOK / NCHUNK);

    auto issue = [&](int stage, int it) {
        const uint32_t sbq = sb + stage * P1_STAGE;
        const uint32_t sbk = sbq + 8192;
        const int c0 = cbase + it * 64;
#pragma unroll
        for (int i = 0; i < 4; i++) {
            const int row = lr0 + i * 16;
            const uint32_t so = SWZ((uint32_t)(row * 128 + lu * 16));
            cp16(sbq + so, qb + (size_t)(c0 + row) * DIM + lu * 8);
            cp16(sbk + so, kb + (size_t)(c0 + row) * DIM + lu * 8);
        }
        CP_COMMIT();
    };

    issue(0, 0);
    issue(1, 1);

    float acc[8][4];
#pragma unroll
    for (int in = 0; in < 8; in++)
#pragma unroll
        for (int j = 0; j < 4; j++) acc[in][j] = 0.0f;

    const int g  = lane >> 3, rr = lane & 7;
    const int toksel = ((g >> 1) << 3) + rr;
    const int dimsel = (g & 1) << 3;

    for (int it = 0; it < 16; it++) {
        if (it == 15) { CP_WAIT(0); } else { CP_WAIT(1); }
        __syncthreads();
        const uint32_t stq = sb + (it & 1) * P1_STAGE;
        const uint32_t stk = stq + 8192;
#pragma unroll
        for (int ks = 0; ks < 4; ks++) {
            const int tok = ks * 16 + toksel;
            uint32_t ah[4];
            LDSM4T(ah, stq + SWZ((uint32_t)(tok * 128 + (w * 16 + dimsel) * 2)));
            uint32_t bh2[8][2];
#pragma unroll
            for (int jb = 0; jb < 4; jb++) {
                uint32_t qh[4];
                LDSM4T(qh, stk + SWZ((uint32_t)(tok * 128 + (jb * 16 + dimsel) * 2)));
                bh2[2 * jb][0] = qh[0]; bh2[2 * jb][1] = qh[2];
                bh2[2 * jb + 1][0] = qh[1]; bh2[2 * jb + 1][1] = qh[3];
            }
#pragma unroll
            for (int in = 0; in < 8; in++)
                MMA16816F(acc[in], ah, bh2[in]);
        }
        if (it + 2 < 16) { __syncthreads(); issue(it & 1, it + 2); }
    }

    const int r0 = lane >> 2, cp = (lane & 3) * 2;
    float* Abh = Ap + ((size_t)ch * 64 + bh) * (HD * HD);
#pragma unroll
    for (int in = 0; in < 8; in++) {
        const int m = in * 8 + cp;
#pragma unroll
        for (int half = 0; half < 2; half++) {
            const int n = w * 16 + r0 + half * 8;
            *(float2*)(Abh + n * 64 + m) =
                make_float2(acc[in][half * 2], acc[in][half * 2 + 1]);
        }
    }
}

// ---------------------------------------------------------------------------
// Reduce partials -> A fp16 + z
// ---------------------------------------------------------------------------
__global__ __launch_bounds__(256)
void attn_reduce(const float* __restrict__ Ap, __half* __restrict__ Ah,
                 float* __restrict__ gZ)
{
    const int bh = blockIdx.x, t = threadIdx.x;
    const int row = t >> 2, qp = t & 3;
    float s[16];
#pragma unroll
    for (int j = 0; j < 16; j++) s[j] = 0.0f;
    for (int c = 0; c < NCHUNK; c++) {
        const float* p = Ap + ((size_t)c * 64 + bh) * (HD * HD) + row * 64 + qp * 16;
#pragma unroll
        for (int j = 0; j < 16; j += 4) {
            float4 v4 = *(const float4*)(p + j);
            s[j] += v4.x; s[j + 1] += v4.y; s[j + 2] += v4.z; s[j + 3] += v4.w;
        }
    }
    alignas(16) __half hv[16];
    float rp = 0.0f;
#pragma unroll
    for (int j = 0; j < 16; j++) { rp += s[j]; hv[j] = __float2half_rn(s[j]); }
    uint4* dst = (uint4*)(Ah + (size_t)bh * (HD * HD) + row * 64 + qp * 16);
    dst[0] = ((uint4*)hv)[0];
    dst[1] = ((uint4*)hv)[1];
    rp += __shfl_xor_sync(0xffffffffu, rp, 1);
    rp += __shfl_xor_sync(0xffffffffu, rp, 2);
    if (qp == 0)
        gZ[bh * HD + row] = 1.0f / (SCALE * rp + (float)DIM);
}

// ---------------------------------------------------------------------------
// Tensor-core attention pass 2 (R15)
// ---------------------------------------------------------------------------
__global__ __launch_bounds__(128)
void attn_pass2t(const __half* __restrict__ v, const __half* __restrict__ gg,
                 const __half* __restrict__ Ah, const float* __restrict__ gZ,
                 __half* __restrict__ Yh)
{
    __shared__ __align__(16) char As_s[8192];
    __shared__ __align__(16) char vs_s[8192];
    __shared__ float zs[64];
    const int bh = blockIdx.x, b = bh >> 4, h = bh & 15;
    const int c0 = blockIdx.y * 64;
    const int t = threadIdx.x, lane = t & 31, w = t >> 5;
    const uint32_t sA = smem_u32(As_s), sV = smem_u32(vs_s);

    {
        const uint4* Ag = (const uint4*)(Ah + (size_t)bh * (HD * HD));
        const __half* vb = v + (size_t)(b * NTOK + c0) * DIM + h * HD;
        for (int i = t; i < 512; i += 128) {
            const int row = i >> 3, un = i & 7;
            const uint32_t so = SWZ((uint32_t)(row * 128 + un * 16));
            *(uint4*)(As_s + so) = Ag[i];
            *(uint4*)(vs_s + so) = *(const uint4*)(vb + (size_t)row * DIM + un * 8);
        }
        if (t < 64) zs[t] = gZ[bh * HD + t];
    }
    __syncthreads();

    float acc[8][4];
#pragma unroll
    for (int in = 0; in < 8; in++)
#pragma unroll
        for (int j = 0; j < 4; j++) acc[in][j] = 0.0f;

    const int g = lane >> 3, rr = lane & 7;
#pragma unroll
    for (int ks = 0; ks < 4; ks++) {
        const int ku = ks * 2 + (g >> 1);
        uint32_t ah[4];
        {
            const int row = w * 16 + ((g & 1) << 3) + rr;
            LDSM4(ah, sV + SWZ((uint32_t)(row * 128 + ku * 16)));
        }
        uint32_t bh2[8][2];
#pragma unroll
        for (int jb = 0; jb < 4; jb++) {
            const int row = jb * 16 + ((g & 1) << 3) + rr;
            uint32_t qh[4];
            LDSM4(qh, sA + SWZ((uint32_t)(row * 128 + ku * 16)));
            bh2[2 * jb][0] = qh[0]; bh2[2 * jb][1] = qh[2];
            bh2[2 * jb + 1][0] = qh[1]; bh2[2 * jb + 1][1] = qh[3];
        }
#pragma unroll
        for (int in = 0; in < 8; in++)
            MMA16816F(acc[in], ah, bh2[in]);
    }

    const int r0 = lane >> 2, cp = (lane & 3) * 2;
#pragma unroll
    for (int in = 0; in < 8; in++) {
        const int n = in * 8 + cp;
#pragma unroll
        for (int half = 0; half < 2; half++) {
            const int dl = w * 16 + r0 + half * 8;
            const int tok = c0 + dl;
            __half2 vv = *(__half2*)(vs_s + SWZ((uint32_t)(dl * 128 + n * 2)));
            float2 vf = __half22float2(vv);
            __half2 gv = *(const __half2*)(gg + (size_t)(b * NTOK + tok) * DIM + h * HD + n);
            float2 gf = __half22float2(gv);
            float o0 = (SCALE * acc[in][half * 2]     + vf.x) * zs[n]     * gf.x;
            float o1 = (SCALE * acc[in][half * 2 + 1] + vf.y) * zs[n + 1] * gf.y;
            const int row = b * NTOK + h * 256 + (tok >> 4);
            const int col = ((tok & 15) << 6) + n;
            *(__half2*)(Yh + (size_t)row * DIM + col) =
                __halves2half2(__float2half_rn(o0), __float2half_rn(o1));
        }
    }
}

// ---------------------------------------------------------------------------
// Launch — R15 DAG, gemm at enqueue position 6 (for ncu -s 5 -c 1)
// ---------------------------------------------------------------------------
extern "C" void kernel_launch(void* const* d_in, const int* in_sizes, int n_in,
                              void* d_out, int out_size)
{
    const float* x    = (const float*)d_in[0];
    const float* q_w1 = (const float*)d_in[1];
    const float* q_b1 = (const float*)d_in[2];
    const float* q_w2 = (const float*)d_in[3];
    const float* q_b2 = (const float*)d_in[4];
    const float* k_w1 = (const float*)d_in[5];
    const float* k_b1 = (const float*)d_in[6];
    const float* k_w2 = (const float*)d_in[7];
    const float* k_b2 = (const float*)d_in[8];
    const float* v_w  = (const float*)d_in[9];
    const float* v_b  = (const float*)d_in[10];
    const float* g_w  = (const float*)d_in[11];
    const float* g_b  = (const float*)d_in[12];
    const float* p_w  = (const float*)d_in[13];
    const float* p_b  = (const float*)d_in[14];
    float* out = (float*)d_out;

    __half *xh, *hqh, *hkh, *yh, *wh, *qb, *kb, *vb, *gb, *Ahp;
    float *zb, *Apb;
    cudaGetSymbolAddress((void**)&xh,  g_x_h);
    cudaGetSymbolAddress((void**)&hqh, g_hq_h);
    cudaGetSymbolAddress((void**)&hkh, g_hk_h);
    cudaGetSymbolAddress((void**)&yh,  g_y_h);
    cudaGetSymbolAddress((void**)&wh,  g_w_h);
    cudaGetSymbolAddress((void**)&qb,  g_q);
    cudaGetSymbolAddress((void**)&kb,  g_k);
    cudaGetSymbolAddress((void**)&vb,  g_v);
    cudaGetSymbolAddress((void**)&gb,  g_g);
    cudaGetSymbolAddress((void**)&Ahp, g_A_h);
    cudaGetSymbolAddress((void**)&zb,  g_z);
    cudaGetSymbolAddress((void**)&Apb, g_Ap);

    static bool init_done = false;
    static cudaStream_t s1, s2, s3;
    static cudaEvent_t ev_fork, ev_x, ev_qw1, ev_qw2, ev_kw1, ev_kw2,
                       ev_pw, ev_k2, ev_v, ev_g;
    if (!init_done) {
        cudaFuncSetAttribute(gemm_mma, cudaFuncAttributeMaxDynamicSharedMemorySize, GSMEM_TOTAL);
        cudaStreamCreateWithFlags(&s1, cudaStreamNonBlocking);
        cudaStreamCreateWithFlags(&s2, cudaStreamNonBlocking);
        cudaStreamCreateWithFlags(&s3, cudaStreamNonBlocking);
        cudaEventCreateWithFlags(&ev_fork, cudaEventDisableTiming);
        cudaEventCreateWithFlags(&ev_x,    cudaEventDisableTiming);
        cudaEventCreateWithFlags(&ev_qw1,  cudaEventDisableTiming);
        cudaEventCreateWithFlags(&ev_qw2,  cudaEventDisableTiming);
        cudaEventCreateWithFlags(&ev_kw1,  cudaEventDisableTiming);
        cudaEventCreateWithFlags(&ev_kw2,  cudaEventDisableTiming);
        cudaEventCreateWithFlags(&ev_pw,   cudaEventDisableTiming);
        cudaEventCreateWithFlags(&ev_k2,   cudaEventDisableTiming);
        cudaEventCreateWithFlags(&ev_v,    cudaEventDisableTiming);
        cudaEventCreateWithFlags(&ev_g,    cudaEventDisableTiming);
        init_done = true;
    }

    const int WSZ = DIM * DIM;
    const int W8  = WSZ / 8;
#define WH(i) (wh + (size_t)(i) * WSZ)

    dim3 ggrid(DIM / 128, MROWS / 128);   // (8, 128)

    // === fork ===
    cudaEventRecord(ev_fork, 0);
    cudaStreamWaitEvent(s1, ev_fork, 0);
    cudaStreamWaitEvent(s2, ev_fork, 0);
    cudaStreamWaitEvent(s3, ev_fork, 0);

    // #1: x convert (s0, critical head)
    conv_f2h_w<<<2048, 256>>>((const float4*)x, (uint4*)xh, MROWS * DIM / 8);
    cudaEventRecord(ev_x, 0);

    // #2-#5: q/k weight converts
    conv_f2h_w<<<592, 256, 0, s1>>>((const float4*)q_w1, (uint4*)WH(0), W8);
    cudaEventRecord(ev_qw1, s1);
    conv_f2h_w<<<592, 256, 0, s1>>>((const float4*)q_w2, (uint4*)WH(1), W8);
    cudaEventRecord(ev_qw2, s1);
    conv_f2h_w<<<592, 256, 0, s2>>>((const float4*)k_w1, (uint4*)WH(2), W8);
    cudaEventRecord(ev_kw1, s2);
    conv_f2h_w<<<592, 256, 0, s2>>>((const float4*)k_w2, (uint4*)WH(3), W8);
    cudaEventRecord(ev_kw2, s2);

    // #6: FIRST GEMM (q1) — the launch ncu profiles
    cudaStreamWaitEvent(0, ev_qw1, 0);
    gemm_mma<<<ggrid, 256, GSMEM_TOTAL>>>(xh, WH(0), q_b1, 1, 1, nullptr, hqh);

    // remaining converts
    conv_f2h_w<<<592, 256, 0, s2>>>((const float4*)v_w, (uint4*)WH(4), W8);
    conv_f2h_w<<<592, 256, 0, s3>>>((const float4*)g_w, (uint4*)WH(5), W8);
    conv_f2h_w<<<592, 256, 0, s3>>>((const float4*)p_w, (uint4*)WH(6), W8);
    cudaEventRecord(ev_pw, s3);

    // k chain on s1
    cudaStreamWaitEvent(s1, ev_x, 0);
    cudaStreamWaitEvent(s1, ev_kw1, 0);
    gemm_mma<<<ggrid, 256, GSMEM_TOTAL, s1>>>(xh, WH(2), k_b1, 1, 1, nullptr, hkh);
    // q2 on s0
    cudaStreamWaitEvent(0, ev_qw2, 0);
    gemm_mma<<<ggrid, 256, GSMEM_TOTAL>>>(hqh, WH(1), q_b2, 2, 1, nullptr, qb);
    // k2 on s1
    cudaStreamWaitEvent(s1, ev_kw2, 0);
    gemm_mma<<<ggrid, 256, GSMEM_TOTAL, s1>>>(hkh, WH(3), k_b2, 2, 1, nullptr, kb);
    cudaEventRecord(ev_k2, s1);

    // v, g GEMMs trail (overlap with attention pass 1)
    cudaStreamWaitEvent(s2, ev_x, 0);
    gemm_mma<<<ggrid, 256, GSMEM_TOTAL, s2>>>(xh, WH(4), v_b, 1, 1, nullptr, vb);
    cudaEventRecord(ev_v, s2);
    cudaStreamWaitEvent(s3, ev_x, 0);
    gemm_mma<<<ggrid, 256, GSMEM_TOTAL, s3>>>(xh, WH(5), g_b, 1, 1, nullptr, gb);
    cudaEventRecord(ev_g, s3);

    // attention (tensor-core)
    cudaStreamWaitEvent(0, ev_k2, 0);
    attn_pass1t<<<dim3(BATCH * NHEAD, NCHUNK), 128, P1_SMEM>>>(qb, kb, Apb);
    attn_reduce<<<BATCH * NHEAD, 256>>>(Apb, Ahp, zb);

    cudaStreamWaitEvent(0, ev_v, 0);
    cudaStreamWaitEvent(0, ev_g, 0);
    attn_pass2t<<<dim3(BATCH * NHEAD, NTOK / 64), 128>>>(vb, gb, Ahp, zb, yh);

    // final projection
    cudaStreamWaitEvent(0, ev_pw, 0);
    gemm_mma<<<ggrid, 256, GSMEM_TOTAL>>>(yh, WH(6), p_b, 0, 0, out, nullptr);
}